// round 13
// baseline (speedup 1.0000x reference)
#include <cuda_runtime.h>

// TensorProduct: out[b,0,n,f] = sum_{l,m} x1[b,0,l,f]*x2[b,0,m,f]*cg[l,m,n] * pe[0]
//                out[b,1,n,f] = same * pe[1]
//
// Shapes: x1 (2048,1,9,512) f32, x2 (2048,1,9,512) f32, cg (9,9,25) f32,
//         parity_even (2,1) f32, out (2048,2,25,512) f32.
//
// R13 = R10 (zero-fill inside LDG shadow, even/odd l3-split CTA pairs, CG
// swap-symmetry folding, streaming stores) at HALF CTA WIDTH: 128 threads,
// grid 8192. Finer pass-A/pass-B interleave -> shorter wave straggler tail,
// smaller store bursts, cheaper barriers. Same occupancy (regs ~64).

#define F2 256           // 512 floats per row = 256 float2
#define TPB 128

template<int L3LO, int L3HI, int NACC>
__device__ __forceinline__ void run_pass(
    const float2 (&a)[9], const float2 (&c)[9],
    const float* __restrict__ scg,
    float pe0, float pe1, bool prescaled,
    float2* __restrict__ O)
{
    float2 acc[NACC];
    #pragma unroll
    for (int q = 0; q < NACC; q++) acc[q] = make_float2(0.f, 0.f);

    #pragma unroll
    for (int i = 0; i < 9; i++) {
        const int l1 = (i >= 4) ? 2 : (i >= 1) ? 1 : 0;
        const int m1 = i - l1 * (l1 + 1);
        const int a1 = m1 < 0 ? -m1 : m1;
        #pragma unroll
        for (int j = i; j < 9; j++) {
            const int l2 = (j >= 4) ? 2 : (j >= 1) ? 1 : 0;
            const int m2 = j - l2 * (l2 + 1);
            const int a2 = m2 < 0 ? -m2 : m2;

            const int lo = (l1 > l2) ? (l1 - l2) : (l2 - l1);
            const int hi = l1 + l2;
            if (hi < L3LO || lo > L3HI) continue;   // pass has no l3 here

            float2 pp, pm;
            if (i == j) {
                pp.x = a[i].x * c[i].x;
                pp.y = a[i].y * c[i].y;
                pm = pp;                 // never used (odd-l3 diag skipped)
            } else {
                float ux = a[i].x * c[j].x, uy = a[i].y * c[j].y;
                float vx = a[j].x * c[i].x, vy = a[j].y * c[i].y;
                pp.x = ux + vx;  pp.y = uy + vy;
                pm.x = ux - vx;  pm.y = uy - vy;
            }

            #pragma unroll
            for (int l3 = 0; l3 <= 4; l3++) {
                if (l3 < L3LO || l3 > L3HI || l3 < lo || l3 > hi) continue;
                const bool neg = ((l1 + l2 + l3) & 1) != 0;
                if (i == j && neg) continue;   // antisymmetric block: diag = 0

                #pragma unroll
                for (int m3 = -4; m3 <= 4; m3++) {
                    if (m3 < -l3 || m3 > l3) continue;
                    const int a3 = m3 < 0 ? -m3 : m3;
                    const bool sel = (a3 == a1 + a2) ||
                                     (a3 == a1 - a2) ||
                                     (a3 == a2 - a1);
                    const int par = (l1 + l2 + l3 + a1 + a2 + a3 +
                                     (m1 < 0 ? 1 : 0) +
                                     (m2 < 0 ? 1 : 0) +
                                     (m3 < 0 ? 1 : 0)) & 1;
                    if (!sel || par) continue;

                    const int k = l3 * (l3 + 1) + m3;   // global n
                    const int q = k - L3LO * L3LO;      // pass-local
                    const float w = scg[(i * 9 + j) * 25 + k];
                    const float2 t = neg ? pm : pp;     // compile-time select
                    acc[q].x = fmaf(w, t.x, acc[q].x);
                    acc[q].y = fmaf(w, t.y, acc[q].y);
                }
            }
        }
    }

    if (prescaled) {
        #pragma unroll
        for (int q = 0; q < NACC; q++) {
            const int n = L3LO * L3LO + q;
            __stcs(&O[n * F2], acc[q]);
        }
    } else {
        #pragma unroll
        for (int q = 0; q < NACC; q++) {
            const int n = L3LO * L3LO + q;
            float2 v0 = make_float2(pe0 * acc[q].x, pe0 * acc[q].y);
            float2 v1 = make_float2(pe1 * acc[q].x, pe1 * acc[q].y);
            __stcs(&O[n * F2], v0);
            __stcs(&O[(25 + n) * F2], v1);
        }
    }
}

__global__ void __launch_bounds__(TPB)
tp_kernel(const float* __restrict__ x1,
          const float* __restrict__ x2,
          const float* __restrict__ cg,
          const float* __restrict__ pe,
          float* __restrict__ out)
{
    __shared__ float scg[9 * 9 * 25];   // 8100 B

    const float pe0 = pe[0];
    const float pe1 = pe[1];
    const bool prescaled = (pe1 == 0.0f);   // uniform branch

    const int cid  = blockIdx.x;                      // 0..8191
    const int pass = cid & 1;
    const int tile = cid >> 1;                        // 0..4095
    const int g    = tile * TPB + threadIdx.x;        // 0..524287
    const int f2   = g & (F2 - 1);
    const int b    = g >> 8;

    const float2* __restrict__ X1 =
        reinterpret_cast<const float2*>(x1) + (size_t)b * 9 * F2 + f2;
    const float2* __restrict__ X2 =
        reinterpret_cast<const float2*>(x2) + (size_t)b * 9 * F2 + f2;

    // ---- Phase 1: ISSUE the input loads first (long-scoreboard in flight) ----
    const float s = prescaled ? pe0 : 1.0f;
    float2 a[9], c[9];
    #pragma unroll
    for (int l = 0; l < 9; l++) {
        float2 v = X1[l * F2];
        a[l] = make_float2(s * v.x, s * v.y);
    }
    #pragma unroll
    for (int l = 0; l < 9; l++) c[l] = X2[l * F2];

    // ---- Phase 2: stage CG in shared (LDG+STS, also in the shadow) ----
    for (int t = threadIdx.x; t < 9 * 9 * 25; t += TPB)
        scg[t] = cg[t];

    // ---- Phase 3: zero-fill of the odd plane INSIDE the load shadow ----
    // Odd plane total: 2048 * 3200 float4. 8192 CTAs each zero a contiguous
    // 800-float4 (12.8KB) chunk: 6 rounds of 128 + 32 tail.
    if (prescaled) {
        float4* __restrict__ P = reinterpret_cast<float4*>(out)
                                 + (size_t)(cid >> 2) * 6400 + 3200
                                 + (cid & 3) * 800;
        const float4 zero = make_float4(0.f, 0.f, 0.f, 0.f);
        const int t = threadIdx.x;
        #pragma unroll
        for (int k = 0; k < 6; k++)          // 6*128 = 768 float4
            __stcs(&P[t + k * 128], zero);
        if (t < 32)                          // tail: 800-768 = 32
            __stcs(&P[t + 768], zero);
    }

    __syncthreads();   // scg visible (drains STS; STGs keep streaming)

    float2* __restrict__ O =
        reinterpret_cast<float2*>(out) + (size_t)b * 50 * F2 + f2;

    if (pass == 0) {
        run_pass<0, 2, 9>(a, c, scg, pe0, pe1, prescaled, O);   // n = 0..8
    } else {
        run_pass<3, 4, 16>(a, c, scg, pe0, pe1, prescaled, O);  // n = 9..24
    }
}

extern "C" void kernel_launch(void* const* d_in, const int* in_sizes, int n_in,
                              void* d_out, int out_size)
{
    const float* x1 = (const float*)d_in[0];
    const float* x2 = (const float*)d_in[1];
    const float* cg = (const float*)d_in[2];
    const float* pe = (const float*)d_in[3];
    float* out = (float*)d_out;

    // 8192 CTAs of 128 threads: even/odd l3-split pairs at fine granularity;
    // each CTA zero-fills a contiguous odd-plane chunk in its load shadow.
    tp_kernel<<<8192, TPB>>>(x1, x2, cg, pe, out);
}

// round 14
// speedup vs baseline: 1.1353x; 1.1353x over previous
#include <cuda_runtime.h>

// TensorProduct: out[b,0,n,f] = sum_{l,m} x1[b,0,l,f]*x2[b,0,m,f]*cg[l,m,n] * pe[0]
//                out[b,1,n,f] = same * pe[1]
//
// Shapes: x1 (2048,1,9,512) f32, x2 (2048,1,9,512) f32, cg (9,9,25) f32,
//         parity_even (2,1) f32, out (2048,2,25,512) f32.
//
// R14 = R10 verbatim (zero-fill inside LDG shadow, even/odd l3-split CTA
// pairs, CG swap-symmetry folding, streaming result stores) with ONE change:
// the odd-plane zero-fill uses st.global.wt (write-through, no L2 allocate)
// so the 105MB zero stream stops churning L2 and the x1/x2 working set stays
// resident. Result stores remain __stcs.

#define F2 256           // 512 floats per row = 256 float2

__device__ __forceinline__ void stwt_f4(float4* p, float4 v) {
    asm volatile("st.global.wt.v4.f32 [%0], {%1, %2, %3, %4};"
                 :: "l"(p), "f"(v.x), "f"(v.y), "f"(v.z), "f"(v.w)
                 : "memory");
}

template<int L3LO, int L3HI, int NACC>
__device__ __forceinline__ void run_pass(
    const float2 (&a)[9], const float2 (&c)[9],
    const float* __restrict__ scg,
    float pe0, float pe1, bool prescaled,
    float2* __restrict__ O)
{
    float2 acc[NACC];
    #pragma unroll
    for (int q = 0; q < NACC; q++) acc[q] = make_float2(0.f, 0.f);

    #pragma unroll
    for (int i = 0; i < 9; i++) {
        const int l1 = (i >= 4) ? 2 : (i >= 1) ? 1 : 0;
        const int m1 = i - l1 * (l1 + 1);
        const int a1 = m1 < 0 ? -m1 : m1;
        #pragma unroll
        for (int j = i; j < 9; j++) {
            const int l2 = (j >= 4) ? 2 : (j >= 1) ? 1 : 0;
            const int m2 = j - l2 * (l2 + 1);
            const int a2 = m2 < 0 ? -m2 : m2;

            const int lo = (l1 > l2) ? (l1 - l2) : (l2 - l1);
            const int hi = l1 + l2;
            if (hi < L3LO || lo > L3HI) continue;   // pass has no l3 here

            float2 pp, pm;
            if (i == j) {
                pp.x = a[i].x * c[i].x;
                pp.y = a[i].y * c[i].y;
                pm = pp;                 // never used (odd-l3 diag skipped)
            } else {
                float ux = a[i].x * c[j].x, uy = a[i].y * c[j].y;
                float vx = a[j].x * c[i].x, vy = a[j].y * c[i].y;
                pp.x = ux + vx;  pp.y = uy + vy;
                pm.x = ux - vx;  pm.y = uy - vy;
            }

            #pragma unroll
            for (int l3 = 0; l3 <= 4; l3++) {
                if (l3 < L3LO || l3 > L3HI || l3 < lo || l3 > hi) continue;
                const bool neg = ((l1 + l2 + l3) & 1) != 0;
                if (i == j && neg) continue;   // antisymmetric block: diag = 0

                #pragma unroll
                for (int m3 = -4; m3 <= 4; m3++) {
                    if (m3 < -l3 || m3 > l3) continue;
                    const int a3 = m3 < 0 ? -m3 : m3;
                    const bool sel = (a3 == a1 + a2) ||
                                     (a3 == a1 - a2) ||
                                     (a3 == a2 - a1);
                    const int par = (l1 + l2 + l3 + a1 + a2 + a3 +
                                     (m1 < 0 ? 1 : 0) +
                                     (m2 < 0 ? 1 : 0) +
                                     (m3 < 0 ? 1 : 0)) & 1;
                    if (!sel || par) continue;

                    const int k = l3 * (l3 + 1) + m3;   // global n
                    const int q = k - L3LO * L3LO;      // pass-local
                    const float w = scg[(i * 9 + j) * 25 + k];
                    const float2 t = neg ? pm : pp;     // compile-time select
                    acc[q].x = fmaf(w, t.x, acc[q].x);
                    acc[q].y = fmaf(w, t.y, acc[q].y);
                }
            }
        }
    }

    if (prescaled) {
        #pragma unroll
        for (int q = 0; q < NACC; q++) {
            const int n = L3LO * L3LO + q;
            __stcs(&O[n * F2], acc[q]);
        }
    } else {
        #pragma unroll
        for (int q = 0; q < NACC; q++) {
            const int n = L3LO * L3LO + q;
            float2 v0 = make_float2(pe0 * acc[q].x, pe0 * acc[q].y);
            float2 v1 = make_float2(pe1 * acc[q].x, pe1 * acc[q].y);
            __stcs(&O[n * F2], v0);
            __stcs(&O[(25 + n) * F2], v1);
        }
    }
}

__global__ void __launch_bounds__(256)
tp_kernel(const float* __restrict__ x1,
          const float* __restrict__ x2,
          const float* __restrict__ cg,
          const float* __restrict__ pe,
          float* __restrict__ out)
{
    __shared__ float scg[9 * 9 * 25];   // 8100 B

    const float pe0 = pe[0];
    const float pe1 = pe[1];
    const bool prescaled = (pe1 == 0.0f);   // uniform branch

    const int cid  = blockIdx.x;                      // 0..4095
    const int pass = cid & 1;
    const int tile = cid >> 1;                        // 0..2047
    const int g    = tile * blockDim.x + threadIdx.x; // 0..524287
    const int f2   = g & (F2 - 1);
    const int b    = g >> 8;

    const float2* __restrict__ X1 =
        reinterpret_cast<const float2*>(x1) + (size_t)b * 9 * F2 + f2;
    const float2* __restrict__ X2 =
        reinterpret_cast<const float2*>(x2) + (size_t)b * 9 * F2 + f2;

    // ---- Phase 1: ISSUE the input loads first (long-scoreboard in flight) ----
    const float s = prescaled ? pe0 : 1.0f;
    float2 a[9], c[9];
    #pragma unroll
    for (int l = 0; l < 9; l++) {
        float2 v = X1[l * F2];
        a[l] = make_float2(s * v.x, s * v.y);
    }
    #pragma unroll
    for (int l = 0; l < 9; l++) c[l] = X2[l * F2];

    // ---- Phase 2: stage CG in shared (LDG+STS, also in the shadow) ----
    for (int t = threadIdx.x; t < 9 * 9 * 25; t += blockDim.x)
        scg[t] = cg[t];

    // ---- Phase 3: zero-fill of the odd plane INSIDE the load shadow ----
    // st.global.wt: write-through, no L2 allocation -> zero stream does not
    // evict the x1/x2 working set. 4096 CTAs each zero a contiguous
    // 1600-float4 (25.6KB) chunk.
    if (prescaled) {
        const int half = cid >> 1;
        const int part = cid & 1;
        float4* __restrict__ P = reinterpret_cast<float4*>(out)
                                 + (size_t)half * 6400 + 3200 + part * 1600;
        const float4 zero = make_float4(0.f, 0.f, 0.f, 0.f);
        const int t = threadIdx.x;
        #pragma unroll
        for (int k = 0; k < 6; k++)          // 6*256 = 1536 float4
            stwt_f4(&P[t + k * 256], zero);
        if (t < 64)                          // tail: 1600-1536 = 64
            stwt_f4(&P[t + 1536], zero);
    }

    __syncthreads();   // scg visible (drains STS; STGs keep streaming)

    float2* __restrict__ O =
        reinterpret_cast<float2*>(out) + (size_t)b * 50 * F2 + f2;

    if (pass == 0) {
        run_pass<0, 2, 9>(a, c, scg, pe0, pe1, prescaled, O);   // n = 0..8
    } else {
        run_pass<3, 4, 16>(a, c, scg, pe0, pe1, prescaled, O);  // n = 9..24
    }
}

extern "C" void kernel_launch(void* const* d_in, const int* in_sizes, int n_in,
                              void* d_out, int out_size)
{
    const float* x1 = (const float*)d_in[0];
    const float* x2 = (const float*)d_in[1];
    const float* cg = (const float*)d_in[2];
    const float* pe = (const float*)d_in[3];
    float* out = (float*)d_out;

    // 4096 compute CTAs (even/odd l3-split pairs); each streams a contiguous
    // odd-plane zero chunk (write-through) inside its own input-load shadow.
    tp_kernel<<<4096, 256>>>(x1, x2, cg, pe, out);
}